// round 3
// baseline (speedup 1.0000x reference)
#include <cuda_runtime.h>
#include <math.h>

// ---------------------------------------------------------------------------
// FourierAttn: out[q,k,b,h] = | prod_d sin(R_h*(qd-kd))/(qd-kd) |
//
// Identity: sin(R(q-k)) = sin(Rq)cos(Rk) - cos(Rq)sin(Rk), rd = Rq - Rk
//   out = | R^16 * (prod_{d<8} s/rd) * (prod_{d>=8} s/rd) |   (2 fast divides)
// Packed f32x2 mainloop: TQ=2 q's ride the two halves of .b64 f32x2 regs.
// k-table pre-baked as duplicated float2 planes: (-Rk,-Rk), (-sinRk,-sinRk),
// (cosRk,cosRk) so the packed path needs zero pack/negate instructions.
// ---------------------------------------------------------------------------

#define QLEN 1024
#define MLEN 1024
#define KLEN 2048
#define BSZ  4
#define NH   8
#define DH   16
#define DM   128
#define BH   32   // BSZ*NH

#define TQ        2
#define BLK_WARPS 8
#define QB        (BLK_WARPS * TQ)   // 16 q per block
#define KT        2                  // k steps staged per tile (24KB smem)
#define KR        512                // k range per block

#define SMALL_T   4e-3f

// k-table: [pos][comp][d][bh] float2 (value duplicated), comp: 0=-Rk 1=-sin 2=cos
__device__ float2 g_ktab[KLEN * 3 * DH * BH];   // ~25 MB
// q-table: [pos][comp][d][bh] float, comp: 0=Rq 1=sin 2=cos
__device__ float  g_qtab[QLEN * 3 * DH * BH];   // ~6.3 MB

// ---------------- packed f32x2 helpers ----------------
union F2 { float2 f; unsigned long long u; };

__device__ __forceinline__ unsigned long long f2add(unsigned long long a, unsigned long long b) {
    unsigned long long d;
    asm("add.rn.f32x2 %0, %1, %2;" : "=l"(d) : "l"(a), "l"(b));
    return d;
}
__device__ __forceinline__ unsigned long long f2mul(unsigned long long a, unsigned long long b) {
    unsigned long long d;
    asm("mul.rn.f32x2 %0, %1, %2;" : "=l"(d) : "l"(a), "l"(b));
    return d;
}
__device__ __forceinline__ unsigned long long f2fma(unsigned long long a, unsigned long long b,
                                                    unsigned long long c) {
    unsigned long long d;
    asm("fma.rn.f32x2 %0, %1, %2, %3;" : "=l"(d) : "l"(a), "l"(b), "l"(c));
    return d;
}
__device__ __forceinline__ F2 f2pack(float lo, float hi) {
    F2 r; r.f.x = lo; r.f.y = hi; return r;
}

// ---------------------------------------------------------------------------
// Setup: projection (pos,b) row @ W column, then R-scale + sincos + table bake
// ---------------------------------------------------------------------------
__global__ void __launch_bounds__(128)
proj_kernel(const float* __restrict__ h,
            const float* __restrict__ mems,
            const float* __restrict__ W,
            const float* __restrict__ paramR,
            int is_k)
{
    int pos = blockIdx.x;
    int b   = blockIdx.y;
    int n   = threadIdx.x;   // 0..127 = head*16 + d

    __shared__ float row[DM];
    const float* src;
    if (is_k)
        src = (pos < MLEN) ? (mems + ((size_t)pos * BSZ + b) * DM)
                           : (h    + ((size_t)(pos - MLEN) * BSZ + b) * DM);
    else
        src = h + ((size_t)pos * BSZ + b) * DM;
    row[n] = src[n];
    __syncthreads();

    float acc = 0.f;
#pragma unroll 8
    for (int m = 0; m < DM; m++)
        acc = fmaf(row[m], W[m * DM + n], acc);

    int hh = n >> 4;
    int d  = n & 15;
    int bh = b * NH + hh;
    float r = paramR[hh] * acc;
    float s, c;
    sincosf(r, &s, &c);

    if (is_k) {
        size_t base = (size_t)pos * 3 * DH * BH;
        g_ktab[base + (0 * DH + d) * BH + bh] = make_float2(-r, -r);
        g_ktab[base + (1 * DH + d) * BH + bh] = make_float2(-s, -s);
        g_ktab[base + (2 * DH + d) * BH + bh] = make_float2( c,  c);
    } else {
        size_t base = (size_t)pos * 3 * DH * BH;
        g_qtab[base + (0 * DH + d) * BH + bh] = r;
        g_qtab[base + (1 * DH + d) * BH + bh] = s;
        g_qtab[base + (2 * DH + d) * BH + bh] = c;
    }
}

// ---------------------------------------------------------------------------
// Main kernel: packed f32x2, block = 16 q x 512 k, lane = bh (coalesced IO)
// ---------------------------------------------------------------------------
__global__ void __launch_bounds__(256, 2)
fourier_kernel(const float* __restrict__ paramR, float* __restrict__ out)
{
    __shared__ float2 sk[KT * 3 * DH * BH];   // 24 KB

    const int lane  = threadIdx.x & 31;   // bh
    const int warp  = threadIdx.x >> 5;
    const int q0    = blockIdx.x * QB + warp * TQ;
    const int q1    = q0 + 1;
    const int kbase = blockIdx.y * KR;

    // q-side: packed pairs (q0, q1) per dim: 48 x 64-bit = 96 regs
    F2 qx2[DH], qs2[DH], qc2[DH];
    {
        const float* t0 = g_qtab + (size_t)q0 * 3 * DH * BH;
        const float* t1 = g_qtab + (size_t)q1 * 3 * DH * BH;
#pragma unroll
        for (int d = 0; d < DH; d++) {
            qx2[d] = f2pack(t0[(0 * DH + d) * BH + lane], t1[(0 * DH + d) * BH + lane]);
            qs2[d] = f2pack(t0[(1 * DH + d) * BH + lane], t1[(1 * DH + d) * BH + lane]);
            qc2[d] = f2pack(t0[(2 * DH + d) * BH + lane], t1[(2 * DH + d) * BH + lane]);
        }
    }

    const F2 cm6  = f2pack(-0.16666667f, -0.16666667f);
    const F2 one2 = f2pack(1.f, 1.f);

    float R  = paramR[lane & 7];
    float r2 = R * R, r4 = r2 * r2, r8 = r4 * r4, r16 = r8 * r8;

    float* out0 = out + (size_t)q0 * (KLEN * BH) + lane;
    float* out1 = out + (size_t)q1 * (KLEN * BH) + lane;

    for (int k0 = kbase; k0 < kbase + KR; k0 += KT) {
        __syncthreads();
        const float2* src = g_ktab + (size_t)k0 * 3 * DH * BH;
#pragma unroll
        for (int i = 0; i < (KT * 3 * DH * BH) / 256; i++)   // 12 float2 per thread
            sk[threadIdx.x + i * 256] = src[threadIdx.x + i * 256];
        __syncthreads();

#pragma unroll
        for (int kk = 0; kk < KT; kk++) {
            F2 na = one2, da = one2, nb = one2, db = one2;

#pragma unroll
            for (int d = 0; d < DH; d++) {
                F2 nkx, nks, kc;
                nkx.f = sk[((kk * 3 + 0) * DH + d) * BH + lane];
                nks.f = sk[((kk * 3 + 1) * DH + d) * BH + lane];
                kc.f  = sk[((kk * 3 + 2) * DH + d) * BH + lane];

                F2 rd; rd.u = f2add(qx2[d].u, nkx.u);            // Rq - Rk (packed)
                F2 t;  t.u  = f2mul(qc2[d].u, nks.u);            // -cos(Rq)sin(Rk)
                F2 s;  s.u  = f2fma(qs2[d].u, kc.u, t.u);        // sin(rd)
                F2 uu; uu.u = f2mul(rd.u, rd.u);
                F2 p;  p.u  = f2fma(uu.u, cm6.u, one2.u);        // 1 - rd^2/6

                bool sa = fabsf(rd.f.x) < SMALL_T;
                bool sb = fabsf(rd.f.y) < SMALL_T;
                F2 nf, df;
                nf.f.x = sa ? p.f.x : s.f.x;   df.f.x = sa ? 1.f : rd.f.x;
                nf.f.y = sb ? p.f.y : s.f.y;   df.f.y = sb ? 1.f : rd.f.y;

                if (d < 8) { na.u = f2mul(na.u, nf.u); da.u = f2mul(da.u, df.u); }
                else       { nb.u = f2mul(nb.u, nf.u); db.u = f2mul(db.u, df.u); }
            }

            int k = k0 + kk;
            // q0 (low halves)
            {
                float ra = __fdividef(na.f.x, da.f.x);
                float rb = __fdividef(nb.f.x, db.f.x);
                out0[(size_t)k * BH] = fabsf(r16 * ra * rb);
            }
            // q1 (high halves)
            {
                float ra = __fdividef(na.f.y, da.f.y);
                float rb = __fdividef(nb.f.y, db.f.y);
                out1[(size_t)k * BH] = fabsf(r16 * ra * rb);
            }
        }
    }
}

// ---------------------------------------------------------------------------
extern "C" void kernel_launch(void* const* d_in, const int* in_sizes, int n_in,
                              void* d_out, int out_size)
{
    (void)in_sizes; (void)n_in; (void)out_size;
    const float* h    = (const float*)d_in[0];
    const float* mems = (const float*)d_in[1];
    const float* Wq   = (const float*)d_in[2];
    const float* Wk   = (const float*)d_in[3];
    const float* R    = (const float*)d_in[4];

    proj_kernel<<<dim3(QLEN, BSZ), DM>>>(h, mems, Wq, R, 0);
    proj_kernel<<<dim3(KLEN, BSZ), DM>>>(h, mems, Wk, R, 1);

    dim3 grid(QLEN / QB, KLEN / KR);   // 64 x 4 = 256 blocks, 1 wave
    fourier_kernel<<<grid, BLK_WARPS * 32>>>(R, (float*)d_out);
}